// round 12
// baseline (speedup 1.0000x reference)
#include <cuda_runtime.h>

// PartialDataLoss: directional Chamfer (template -> scan) with threshold 0.1.
// Scan points binned into a 32^3 grid (cell 0.32 >= sqrt(0.1)); exact 3x3x3
// neighborhood search with geometric row pruning. Clamping to [-5.12,5.12) is
// 1-Lipschitz; distances always use true coordinates.
//
// d2 = |t|^2 + (|s|^2 - 2 t.s); binned points packed as (-2x,-2y,-2z,|s|^2).
//
// 4 launches: count (atomic rank capture) -> scan (int4 prefix sum; also
// re-zeroes g_count for the next graph replay) -> scatter (atomic-free) ->
// query (9-range prefetch, REDUX.MIN warp reduces, row pruning, last-block
// ticket reduction with fixed-order sums).

#define GDIM     32
#define NCELLS   (GDIM * GDIM * GDIM)
#define GMIN     (-5.12f)
#define CELL     0.32f
#define INV_CELL 3.125f          // 1/0.32, exact in fp32
#define THRESH   0.1f

#define N_MAX    65536
#define M_MAX    8192
#define QBLOCK   128
#define QWARPS   (QBLOCK / 32)
#define QB_MAX   ((M_MAX + QWARPS - 1) / QWARPS)

__device__ int      g_count[NCELLS];      // zero at load; re-zeroed by scan
__device__ int      g_start[NCELLS + 4];  // +pad for int4 stores
__device__ unsigned g_rank[N_MAX];        // (cell << 17) | rank (logical shifts)
__device__ float4   g_sorted[N_MAX];
__device__ float    g_blocksum[QB_MAX];
__device__ int      g_ticket;             // zero at load; reset by last block

__device__ __forceinline__ int clamp_cell(float v) {
    int c = __float2int_rd((v - GMIN) * INV_CELL);
    return max(0, min(GDIM - 1, c));
}
// Monotone float->int map: float order == signed int order (non-NaN).
__device__ __forceinline__ int f2ord(float f) {
    int b = __float_as_int(f);
    return b >= 0 ? b : (b ^ 0x7FFFFFFF);
}
__device__ __forceinline__ float ord2f(int b) {
    return __int_as_float(b >= 0 ? b : (b ^ 0x7FFFFFFF));
}

__global__ void count_kernel(const float* __restrict__ scan, int N) {
    int i = blockIdx.x * blockDim.x + threadIdx.x;
    if (i < N) {
        int cx = clamp_cell(scan[3 * i + 0]);
        int cy = clamp_cell(scan[3 * i + 1]);
        int cz = clamp_cell(scan[3 * i + 2]);
        unsigned c = (unsigned)((cx * GDIM + cy) * GDIM + cz);
        unsigned pos = (unsigned)atomicAdd(&g_count[c], 1);
        g_rank[i] = (c << 17) | pos;
    }
}

// Exclusive prefix sum over NCELLS counts; one CTA, int4-vectorized traffic.
// Also zeroes g_count (it has been fully consumed here) for the next replay.
__global__ void __launch_bounds__(1024) scan_kernel() {
    const int tid = threadIdx.x;

    int a[32];
    {
        const int4* c4 = reinterpret_cast<const int4*>(g_count);
#pragma unroll
        for (int k = 0; k < 8; k++) {
            int4 v = c4[tid * 8 + k];
            a[4 * k + 0] = v.x; a[4 * k + 1] = v.y;
            a[4 * k + 2] = v.z; a[4 * k + 3] = v.w;
        }
    }

    int run = 0;
#pragma unroll
    for (int k = 0; k < 32; k++) {
        int t = a[k];
        a[k] = run;
        run += t;
    }

    const int lane = tid & 31, wid = tid >> 5;
    int v = run;
#pragma unroll
    for (int o = 1; o < 32; o <<= 1) {
        int n = __shfl_up_sync(0xFFFFFFFFu, v, o);
        if (lane >= o) v += n;
    }
    __shared__ int wtot[32];
    if (lane == 31) wtot[wid] = v;
    __syncthreads();
    if (wid == 0) {
        int w = wtot[lane];
#pragma unroll
        for (int o = 1; o < 32; o <<= 1) {
            int n = __shfl_up_sync(0xFFFFFFFFu, w, o);
            if (lane >= o) w += n;
        }
        wtot[lane] = w;
    }
    __syncthreads();
    const int offset = (v - run) + (wid > 0 ? wtot[wid - 1] : 0);

    {
        int4* s4 = reinterpret_cast<int4*>(g_start);
        int4* c4 = reinterpret_cast<int4*>(g_count);
        const int4 z4 = make_int4(0, 0, 0, 0);
#pragma unroll
        for (int k = 0; k < 8; k++) {
            s4[tid * 8 + k] = make_int4(a[4 * k + 0] + offset, a[4 * k + 1] + offset,
                                        a[4 * k + 2] + offset, a[4 * k + 3] + offset);
            c4[tid * 8 + k] = z4;     // ready for next graph replay
        }
    }
    if (tid == 1023) g_start[NCELLS] = offset + run;
}

__global__ void scatter_kernel(const float* __restrict__ scan, int N) {
    int i = blockIdx.x * blockDim.x + threadIdx.x;
    if (i < N) {
        unsigned r = g_rank[i];
        int c   = (int)(r >> 17);          // logical shift
        int pos = (int)(r & 0x1FFFFu);
        float x = scan[3 * i + 0], y = scan[3 * i + 1], z = scan[3 * i + 2];
        g_sorted[g_start[c] + pos] = make_float4(-2.f * x, -2.f * y, -2.f * z,
                                                 fmaf(x, x, fmaf(y, y, z * z)));
    }
}

// One warp per template point. All 9 row ranges prefetched up front (MLP~18);
// center z-row processed first; its REDUX.MIN bound (capped at THRESH) prunes
// the remaining rows by slab lower bound dx^2+dy^2.
__global__ void __launch_bounds__(QBLOCK)
query_kernel(const float* __restrict__ tmpl, int M, float* __restrict__ out) {
    const int wid  = threadIdx.x >> 5;
    const int gw   = blockIdx.x * QWARPS + wid;
    const int lane = threadIdx.x & 31;

    float contrib = 0.0f;
    if (gw < M) {
        const float tx = __ldg(&tmpl[3 * gw + 0]);
        const float ty = __ldg(&tmpl[3 * gw + 1]);
        const float tz = __ldg(&tmpl[3 * gw + 2]);
        const float tsq = fmaf(tx, tx, fmaf(ty, ty, tz * tz));

        const int cx = clamp_cell(tx), cy = clamp_cell(ty), cz = clamp_cell(tz);
        const int xlo = max(cx - 1, 0), xhi = min(cx + 1, GDIM - 1);
        const int ylo = max(cy - 1, 0), yhi = min(cy + 1, GDIM - 1);
        const int zlo = max(cz - 1, 0), zhi = min(cz + 1, GDIM - 1);

        // Prefetch all row ranges + slab bounds (independent loads, MLP high).
        int   sA[9], eA[9];
        float bA[9];
        int ns = 0, centerIdx = 0;
        for (int xx = xlo; xx <= xhi; xx++) {
            const float ax = GMIN + xx * CELL, bx = ax + CELL;
            const float dx = (xx == cx) ? 0.f : fmaxf(0.f, fmaxf(ax - tx, tx - bx));
            for (int yy = ylo; yy <= yhi; yy++) {
                const float ay = GMIN + yy * CELL, by = ay + CELL;
                const float dy = (yy == cy) ? 0.f : fmaxf(0.f, fmaxf(ay - ty, ty - by));
                const int row = (xx * GDIM + yy) * GDIM;
                sA[ns] = __ldg(&g_start[row + zlo]);
                eA[ns] = __ldg(&g_start[row + zhi + 1]);
                bA[ns] = fmaf(dx, dx, dy * dy);
                if (xx == cx && yy == cy) centerIdx = ns;
                ns++;
            }
        }

        const float inf = __int_as_float(0x7f800000);
        float mn0 = inf, mn1 = inf, mn2 = inf, mn3 = inf;

        auto do_row = [&](int s, int e) {
            for (int i = s + lane; i < e; i += 128) {
                const int i1 = i + 32, i2 = i + 64, i3 = i + 96;
                float4 p0 = g_sorted[i];
                float4 p1, p2, p3;
                if (i1 < e) p1 = g_sorted[i1];
                if (i2 < e) p2 = g_sorted[i2];
                if (i3 < e) p3 = g_sorted[i3];
                {
                    float a = fmaf(p0.x, tx, p0.w);
                    a = fmaf(p0.y, ty, a); a = fmaf(p0.z, tz, a);
                    mn0 = fminf(mn0, a);
                }
                if (i1 < e) {
                    float a = fmaf(p1.x, tx, p1.w);
                    a = fmaf(p1.y, ty, a); a = fmaf(p1.z, tz, a);
                    mn1 = fminf(mn1, a);
                }
                if (i2 < e) {
                    float a = fmaf(p2.x, tx, p2.w);
                    a = fmaf(p2.y, ty, a); a = fmaf(p2.z, tz, a);
                    mn2 = fminf(mn2, a);
                }
                if (i3 < e) {
                    float a = fmaf(p3.x, tx, p3.w);
                    a = fmaf(p3.y, ty, a); a = fmaf(p3.z, tz, a);
                    mn3 = fminf(mn3, a);
                }
            }
        };

        // Center row first, then REDUX-min bound.
        do_row(sA[centerIdx], eA[centerIdx]);
        float cm = fminf(fminf(mn0, mn1), fminf(mn2, mn3));
        cm = ord2f(__reduce_min_sync(0xFFFFFFFFu, f2ord(cm)));
        const float runb = fminf(THRESH, cm + tsq);

        for (int k = 0; k < ns; k++) {
            if (k == centerIdx) continue;
            if (bA[k] >= runb) continue;       // provably irrelevant
            do_row(sA[k], eA[k]);
        }

        float mn = fminf(fminf(mn0, mn1), fminf(mn2, mn3));
        mn = ord2f(__reduce_min_sync(0xFFFFFFFFu, f2ord(mn)));
        const float d2 = mn + tsq;
        if (d2 < THRESH) contrib = d2;
    }

    __shared__ float ws[QWARPS];
    __shared__ bool amlast;
    if (lane == 0) ws[wid] = contrib;
    __syncthreads();
    if (threadIdx.x == 0) {
        float s = 0.0f;
#pragma unroll
        for (int k = 0; k < QWARPS; k++) s += ws[k];   // fixed order
        g_blocksum[blockIdx.x] = s;
        __threadfence();
        int t = atomicAdd(&g_ticket, 1);
        amlast = (t == (int)gridDim.x - 1);
    }
    __syncthreads();

    if (amlast) {   // deterministic final reduction by the last-arriving block
        __threadfence();
        float s = 0.0f;
        for (int b = threadIdx.x; b < (int)gridDim.x; b += QBLOCK)
            s += g_blocksum[b];                        // fixed strided partition
#pragma unroll
        for (int o = 16; o > 0; o >>= 1)
            s += __shfl_down_sync(0xFFFFFFFFu, s, o);
        if (lane == 0) ws[wid] = s;
        __syncthreads();
        if (threadIdx.x == 0) {
            float tot = 0.0f;
#pragma unroll
            for (int k = 0; k < QWARPS; k++) tot += ws[k];
            out[0] = tot;
            g_ticket = 0;                              // ready for next replay
        }
    }
}

extern "C" void kernel_launch(void* const* d_in, const int* in_sizes, int n_in,
                              void* d_out, int out_size) {
    const float* scan = (const float*)d_in[0];
    const float* tmpl = (const float*)d_in[1];
    const int N = in_sizes[0] / 3;
    const int M = in_sizes[1] / 3;

    count_kernel<<<(N + 255) / 256, 256>>>(scan, N);
    scan_kernel<<<1, 1024>>>();
    scatter_kernel<<<(N + 255) / 256, 256>>>(scan, N);

    const int qblocks = (M + QWARPS - 1) / QWARPS;
    query_kernel<<<qblocks, QBLOCK>>>(tmpl, M, (float*)d_out);
}

// round 13
// speedup vs baseline: 1.0606x; 1.0606x over previous
#include <cuda_runtime.h>

// PartialDataLoss: directional Chamfer (template -> scan) with threshold 0.1.
// Scan points binned into a 32^3 grid (cell 0.32 >= sqrt(0.1)); exact 3x3x3
// neighborhood search with geometric row pruning. Clamping to [-5.12,5.12) is
// 1-Lipschitz; distances always use true coordinates.
//
// d2 = |t|^2 + (|s|^2 - 2 t.s); binned points packed as (-2x,-2y,-2z,|s|^2).
//
// 4 launches: count (atomic rank capture) -> scan (int4 prefix sum; also
// re-zeroes g_count) -> scatter (atomic-free) -> query (register-resident
// 9-range prefetch via fully-unrolled 3x3 loop, REDUX.MIN reduces, row
// pruning, last-block ticket reduction with fixed-order sums).

#define GDIM     32
#define NCELLS   (GDIM * GDIM * GDIM)
#define GMIN     (-5.12f)
#define CELL     0.32f
#define INV_CELL 3.125f          // 1/0.32, exact in fp32
#define THRESH   0.1f

#define N_MAX    65536
#define M_MAX    8192
#define QBLOCK   128
#define QWARPS   (QBLOCK / 32)
#define QB_MAX   ((M_MAX + QWARPS - 1) / QWARPS)

__device__ int      g_count[NCELLS];      // zero at load; re-zeroed by scan
__device__ int      g_start[NCELLS + 4];  // +pad for int4 stores
__device__ unsigned g_rank[N_MAX];        // (cell << 17) | rank (logical shifts)
__device__ float4   g_sorted[N_MAX];
__device__ float    g_blocksum[QB_MAX];
__device__ int      g_ticket;             // zero at load; reset by last block

__device__ __forceinline__ int clamp_cell(float v) {
    int c = __float2int_rd((v - GMIN) * INV_CELL);
    return max(0, min(GDIM - 1, c));
}
// Monotone float->int map: float order == signed int order (non-NaN).
__device__ __forceinline__ int f2ord(float f) {
    int b = __float_as_int(f);
    return b >= 0 ? b : (b ^ 0x7FFFFFFF);
}
__device__ __forceinline__ float ord2f(int b) {
    return __int_as_float(b >= 0 ? b : (b ^ 0x7FFFFFFF));
}

__global__ void count_kernel(const float* __restrict__ scan, int N) {
    int i = blockIdx.x * blockDim.x + threadIdx.x;
    if (i < N) {
        int cx = clamp_cell(scan[3 * i + 0]);
        int cy = clamp_cell(scan[3 * i + 1]);
        int cz = clamp_cell(scan[3 * i + 2]);
        unsigned c = (unsigned)((cx * GDIM + cy) * GDIM + cz);
        unsigned pos = (unsigned)atomicAdd(&g_count[c], 1);
        g_rank[i] = (c << 17) | pos;
    }
}

// Exclusive prefix sum over NCELLS counts; one CTA, int4-vectorized traffic.
// Also zeroes g_count (fully consumed here) for the next graph replay.
__global__ void __launch_bounds__(1024) scan_kernel() {
    const int tid = threadIdx.x;

    int a[32];
    {
        const int4* c4 = reinterpret_cast<const int4*>(g_count);
#pragma unroll
        for (int k = 0; k < 8; k++) {
            int4 v = c4[tid * 8 + k];
            a[4 * k + 0] = v.x; a[4 * k + 1] = v.y;
            a[4 * k + 2] = v.z; a[4 * k + 3] = v.w;
        }
    }

    int run = 0;
#pragma unroll
    for (int k = 0; k < 32; k++) {
        int t = a[k];
        a[k] = run;
        run += t;
    }

    const int lane = tid & 31, wid = tid >> 5;
    int v = run;
#pragma unroll
    for (int o = 1; o < 32; o <<= 1) {
        int n = __shfl_up_sync(0xFFFFFFFFu, v, o);
        if (lane >= o) v += n;
    }
    __shared__ int wtot[32];
    if (lane == 31) wtot[wid] = v;
    __syncthreads();
    if (wid == 0) {
        int w = wtot[lane];
#pragma unroll
        for (int o = 1; o < 32; o <<= 1) {
            int n = __shfl_up_sync(0xFFFFFFFFu, w, o);
            if (lane >= o) w += n;
        }
        wtot[lane] = w;
    }
    __syncthreads();
    const int offset = (v - run) + (wid > 0 ? wtot[wid - 1] : 0);

    {
        int4* s4 = reinterpret_cast<int4*>(g_start);
        int4* c4 = reinterpret_cast<int4*>(g_count);
        const int4 z4 = make_int4(0, 0, 0, 0);
#pragma unroll
        for (int k = 0; k < 8; k++) {
            s4[tid * 8 + k] = make_int4(a[4 * k + 0] + offset, a[4 * k + 1] + offset,
                                        a[4 * k + 2] + offset, a[4 * k + 3] + offset);
            c4[tid * 8 + k] = z4;     // ready for next replay
        }
    }
    if (tid == 1023) g_start[NCELLS] = offset + run;
}

__global__ void scatter_kernel(const float* __restrict__ scan, int N) {
    int i = blockIdx.x * blockDim.x + threadIdx.x;
    if (i < N) {
        unsigned r = g_rank[i];
        int c   = (int)(r >> 17);          // logical shift
        int pos = (int)(r & 0x1FFFFu);
        float x = scan[3 * i + 0], y = scan[3 * i + 1], z = scan[3 * i + 2];
        g_sorted[g_start[c] + pos] = make_float4(-2.f * x, -2.f * y, -2.f * z,
                                                 fmaf(x, x, fmaf(y, y, z * z)));
    }
}

// One warp per template point. The 9 (s,e,bound) row descriptors are built by
// a FULLY UNROLLED 3x3 loop (compile-time k) so they live in registers and
// the 18 g_start loads overlap (MLP~18). Center row (k=4) first; its
// REDUX.MIN bound (capped at THRESH) prunes remaining rows by dx^2+dy^2.
__global__ void __launch_bounds__(QBLOCK)
query_kernel(const float* __restrict__ tmpl, int M, float* __restrict__ out) {
    const int wid  = threadIdx.x >> 5;
    const int gw   = blockIdx.x * QWARPS + wid;
    const int lane = threadIdx.x & 31;

    float contrib = 0.0f;
    if (gw < M) {
        const float tx = __ldg(&tmpl[3 * gw + 0]);
        const float ty = __ldg(&tmpl[3 * gw + 1]);
        const float tz = __ldg(&tmpl[3 * gw + 2]);
        const float tsq = fmaf(tx, tx, fmaf(ty, ty, tz * tz));

        const int cx = clamp_cell(tx), cy = clamp_cell(ty), cz = clamp_cell(tz);
        const int zlo = max(cz - 1, 0), zhi = min(cz + 1, GDIM - 1);

        int   sA[9], eA[9];
        float bA[9];
#pragma unroll
        for (int ix = 0; ix < 3; ix++) {
            const int xx = cx + ix - 1;
            const bool vx = (xx >= 0) && (xx < GDIM);
            const int xxc = min(max(xx, 0), GDIM - 1);
            const float ax = GMIN + xx * CELL;
            const float dx = (ix == 1) ? 0.f
                             : fmaxf(0.f, fmaxf(ax - tx, tx - (ax + CELL)));
#pragma unroll
            for (int iy = 0; iy < 3; iy++) {
                const int k = ix * 3 + iy;            // compile-time index
                const int yy = cy + iy - 1;
                const bool ok = vx && (yy >= 0) && (yy < GDIM);
                const int yyc = min(max(yy, 0), GDIM - 1);
                const float ay = GMIN + yy * CELL;
                const float dy = (iy == 1) ? 0.f
                                 : fmaxf(0.f, fmaxf(ay - ty, ty - (ay + CELL)));
                const int row = (xxc * GDIM + yyc) * GDIM;
                sA[k] = ok ? __ldg(&g_start[row + zlo]) : 0;
                eA[k] = ok ? __ldg(&g_start[row + zhi + 1]) : 0;
                bA[k] = fmaf(dx, dx, dy * dy);
            }
        }

        const float inf = __int_as_float(0x7f800000);
        float mn0 = inf, mn1 = inf, mn2 = inf, mn3 = inf;

        auto do_row = [&](int s, int e) {
            for (int i = s + lane; i < e; i += 128) {
                const int i1 = i + 32, i2 = i + 64, i3 = i + 96;
                float4 p0 = g_sorted[i];
                float4 p1, p2, p3;
                if (i1 < e) p1 = g_sorted[i1];
                if (i2 < e) p2 = g_sorted[i2];
                if (i3 < e) p3 = g_sorted[i3];
                {
                    float a = fmaf(p0.x, tx, p0.w);
                    a = fmaf(p0.y, ty, a); a = fmaf(p0.z, tz, a);
                    mn0 = fminf(mn0, a);
                }
                if (i1 < e) {
                    float a = fmaf(p1.x, tx, p1.w);
                    a = fmaf(p1.y, ty, a); a = fmaf(p1.z, tz, a);
                    mn1 = fminf(mn1, a);
                }
                if (i2 < e) {
                    float a = fmaf(p2.x, tx, p2.w);
                    a = fmaf(p2.y, ty, a); a = fmaf(p2.z, tz, a);
                    mn2 = fminf(mn2, a);
                }
                if (i3 < e) {
                    float a = fmaf(p3.x, tx, p3.w);
                    a = fmaf(p3.y, ty, a); a = fmaf(p3.z, tz, a);
                    mn3 = fminf(mn3, a);
                }
            }
        };

        // Center row (k = 4) first, then REDUX-min bound.
        do_row(sA[4], eA[4]);
        float cm = fminf(fminf(mn0, mn1), fminf(mn2, mn3));
        cm = ord2f(__reduce_min_sync(0xFFFFFFFFu, f2ord(cm)));
        const float runb = fminf(THRESH, cm + tsq);

#pragma unroll
        for (int k = 0; k < 9; k++) {
            if (k == 4) continue;
            if (bA[k] >= runb) continue;       // provably irrelevant
            do_row(sA[k], eA[k]);
        }

        float mn = fminf(fminf(mn0, mn1), fminf(mn2, mn3));
        mn = ord2f(__reduce_min_sync(0xFFFFFFFFu, f2ord(mn)));
        const float d2 = mn + tsq;
        if (d2 < THRESH) contrib = d2;
    }

    __shared__ float ws[QWARPS];
    __shared__ bool amlast;
    if (lane == 0) ws[wid] = contrib;
    __syncthreads();
    if (threadIdx.x == 0) {
        float s = 0.0f;
#pragma unroll
        for (int k = 0; k < QWARPS; k++) s += ws[k];   // fixed order
        g_blocksum[blockIdx.x] = s;
        __threadfence();
        int t = atomicAdd(&g_ticket, 1);
        amlast = (t == (int)gridDim.x - 1);
    }
    __syncthreads();

    if (amlast) {   // deterministic final reduction by the last-arriving block
        __threadfence();
        float s = 0.0f;
        for (int b = threadIdx.x; b < (int)gridDim.x; b += QBLOCK)
            s += g_blocksum[b];                        // fixed strided partition
#pragma unroll
        for (int o = 16; o > 0; o >>= 1)
            s += __shfl_down_sync(0xFFFFFFFFu, s, o);
        if (lane == 0) ws[wid] = s;
        __syncthreads();
        if (threadIdx.x == 0) {
            float tot = 0.0f;
#pragma unroll
            for (int k = 0; k < QWARPS; k++) tot += ws[k];
            out[0] = tot;
            g_ticket = 0;                              // ready for next replay
        }
    }
}

extern "C" void kernel_launch(void* const* d_in, const int* in_sizes, int n_in,
                              void* d_out, int out_size) {
    const float* scan = (const float*)d_in[0];
    const float* tmpl = (const float*)d_in[1];
    const int N = in_sizes[0] / 3;
    const int M = in_sizes[1] / 3;

    count_kernel<<<(N + 255) / 256, 256>>>(scan, N);
    scan_kernel<<<1, 1024>>>();
    scatter_kernel<<<(N + 255) / 256, 256>>>(scan, N);

    const int qblocks = (M + QWARPS - 1) / QWARPS;
    query_kernel<<<qblocks, QBLOCK>>>(tmpl, M, (float*)d_out);
}

// round 15
// speedup vs baseline: 1.2108x; 1.1416x over previous
#include <cuda_runtime.h>

// PartialDataLoss: directional Chamfer (template -> scan) with threshold 0.1.
// Scan points binned into a 32^3 grid (cell 0.32 >= sqrt(0.1)); exact 3x3x3
// neighborhood search with geometric pruning. Clamping to [-5.12,5.12) is
// 1-Lipschitz; distances always use true coordinates. Slab bounds remain
// valid under clamping (outliers enter boundary cells from the valid side;
// degenerate ranges are empty so their bounds are never consulted).
//
// d2 = |t|^2 + (|s|^2 - 2 t.s); binned points packed as (-2x,-2y,-2z,|s|^2).
//
// 4 launches: count (atomic rank capture) -> scan (int4 prefix sum) ->
// scatter (atomic-free; re-zeroes g_count in parallel) -> query (center CELL
// first, REDUX.MIN bound, z + row pruning, last-block ticket reduction).

#define GDIM     32
#define NCELLS   (GDIM * GDIM * GDIM)
#define GMIN     (-5.12f)
#define CELL     0.32f
#define INV_CELL 3.125f          // 1/0.32, exact in fp32
#define THRESH   0.1f

#define N_MAX    65536
#define M_MAX    8192
#define QBLOCK   128
#define QWARPS   (QBLOCK / 32)
#define QB_MAX   ((M_MAX + QWARPS - 1) / QWARPS)

__device__ int      g_count[NCELLS];      // zero at load; re-zeroed by scatter
__device__ int      g_start[NCELLS + 4];  // +pad for int4 stores
__device__ unsigned g_rank[N_MAX];        // (cell << 17) | rank (logical shifts)
__device__ float4   g_sorted[N_MAX];
__device__ float    g_blocksum[QB_MAX];
__device__ int      g_ticket;             // zero at load; reset by last block

__device__ __forceinline__ int clamp_cell(float v) {
    int c = __float2int_rd((v - GMIN) * INV_CELL);
    return max(0, min(GDIM - 1, c));
}
// Monotone float->int map: float order == signed int order (non-NaN).
__device__ __forceinline__ int f2ord(float f) {
    int b = __float_as_int(f);
    return b >= 0 ? b : (b ^ 0x7FFFFFFF);
}
__device__ __forceinline__ float ord2f(int b) {
    return __int_as_float(b >= 0 ? b : (b ^ 0x7FFFFFFF));
}

__global__ void count_kernel(const float* __restrict__ scan, int N) {
    int i = blockIdx.x * blockDim.x + threadIdx.x;
    if (i < N) {
        int cx = clamp_cell(scan[3 * i + 0]);
        int cy = clamp_cell(scan[3 * i + 1]);
        int cz = clamp_cell(scan[3 * i + 2]);
        unsigned c = (unsigned)((cx * GDIM + cy) * GDIM + cz);
        unsigned pos = (unsigned)atomicAdd(&g_count[c], 1);
        g_rank[i] = (c << 17) | pos;
    }
}

// Exclusive prefix sum over NCELLS counts; one CTA, int4-vectorized traffic.
__global__ void __launch_bounds__(1024) scan_kernel() {
    const int tid = threadIdx.x;

    int a[32];
    {
        const int4* c4 = reinterpret_cast<const int4*>(g_count);
#pragma unroll
        for (int k = 0; k < 8; k++) {
            int4 v = c4[tid * 8 + k];
            a[4 * k + 0] = v.x; a[4 * k + 1] = v.y;
            a[4 * k + 2] = v.z; a[4 * k + 3] = v.w;
        }
    }

    int run = 0;
#pragma unroll
    for (int k = 0; k < 32; k++) {
        int t = a[k];
        a[k] = run;
        run += t;
    }

    const int lane = tid & 31, wid = tid >> 5;
    int v = run;
#pragma unroll
    for (int o = 1; o < 32; o <<= 1) {
        int n = __shfl_up_sync(0xFFFFFFFFu, v, o);
        if (lane >= o) v += n;
    }
    __shared__ int wtot[32];
    if (lane == 31) wtot[wid] = v;
    __syncthreads();
    if (wid == 0) {
        int w = wtot[lane];
#pragma unroll
        for (int o = 1; o < 32; o <<= 1) {
            int n = __shfl_up_sync(0xFFFFFFFFu, w, o);
            if (lane >= o) w += n;
        }
        wtot[lane] = w;
    }
    __syncthreads();
    const int offset = (v - run) + (wid > 0 ? wtot[wid - 1] : 0);

    {
        int4* s4 = reinterpret_cast<int4*>(g_start);
#pragma unroll
        for (int k = 0; k < 8; k++)
            s4[tid * 8 + k] = make_int4(a[4 * k + 0] + offset, a[4 * k + 1] + offset,
                                        a[4 * k + 2] + offset, a[4 * k + 3] + offset);
    }
    if (tid == 1023) g_start[NCELLS] = offset + run;
}

__global__ void scatter_kernel(const float* __restrict__ scan, int N) {
    int i = blockIdx.x * blockDim.x + threadIdx.x;
    if (i < N) {
        unsigned r = g_rank[i];
        int c   = (int)(r >> 17);          // logical shift
        int pos = (int)(r & 0x1FFFFu);
        float x = scan[3 * i + 0], y = scan[3 * i + 1], z = scan[3 * i + 2];
        g_sorted[g_start[c] + pos] = make_float4(-2.f * x, -2.f * y, -2.f * z,
                                                 fmaf(x, x, fmaf(y, y, z * z)));
    }
    if (i < NCELLS) g_count[i] = 0;   // parallel re-zero for next graph replay
}

// One warp per template point. Register-resident prefetch of 9 row ranges +
// the center cell's inner boundaries. Center CELL processed first (smallest
// candidate set with the best expected min); REDUX.MIN bound (capped at
// THRESH) then prunes the center row's z-leftovers (dz^2) and the 8 other
// rows (dx^2+dy^2).
__global__ void __launch_bounds__(QBLOCK)
query_kernel(const float* __restrict__ tmpl, int M, float* __restrict__ out) {
    const int wid  = threadIdx.x >> 5;
    const int gw   = blockIdx.x * QWARPS + wid;
    const int lane = threadIdx.x & 31;

    float contrib = 0.0f;
    if (gw < M) {
        const float tx = __ldg(&tmpl[3 * gw + 0]);
        const float ty = __ldg(&tmpl[3 * gw + 1]);
        const float tz = __ldg(&tmpl[3 * gw + 2]);
        const float tsq = fmaf(tx, tx, fmaf(ty, ty, tz * tz));

        const int cx = clamp_cell(tx), cy = clamp_cell(ty), cz = clamp_cell(tz);
        const int zlo = max(cz - 1, 0), zhi = min(cz + 1, GDIM - 1);

        int   sA[9], eA[9];
        float bA[9];
#pragma unroll
        for (int ix = 0; ix < 3; ix++) {
            const int xx = cx + ix - 1;
            const bool vx = (xx >= 0) && (xx < GDIM);
            const int xxc = min(max(xx, 0), GDIM - 1);
            const float ax = GMIN + xx * CELL;
            const float dx = (ix == 1) ? 0.f
                             : fmaxf(0.f, fmaxf(ax - tx, tx - (ax + CELL)));
#pragma unroll
            for (int iy = 0; iy < 3; iy++) {
                const int k = ix * 3 + iy;            // compile-time index
                const int yy = cy + iy - 1;
                const bool ok = vx && (yy >= 0) && (yy < GDIM);
                const int yyc = min(max(yy, 0), GDIM - 1);
                const float ay = GMIN + yy * CELL;
                const float dy = (iy == 1) ? 0.f
                                 : fmaxf(0.f, fmaxf(ay - ty, ty - (ay + CELL)));
                const int row = (xxc * GDIM + yyc) * GDIM;
                sA[k] = ok ? __ldg(&g_start[row + zlo]) : 0;
                eA[k] = ok ? __ldg(&g_start[row + zhi + 1]) : 0;
                bA[k] = fmaf(dx, dx, dy * dy);
            }
        }
        // Center cell's inner boundaries (issued alongside the 18 above).
        const int crow = (cx * GDIM + cy) * GDIM;
        const int scz  = __ldg(&g_start[crow + cz]);
        const int scz1 = __ldg(&g_start[crow + cz + 1]);

        const float inf = __int_as_float(0x7f800000);
        float mn0 = inf, mn1 = inf, mn2 = inf, mn3 = inf;

        auto do_row = [&](int s, int e) {
            for (int i = s + lane; i < e; i += 128) {
                const int i1 = i + 32, i2 = i + 64, i3 = i + 96;
                float4 p0 = g_sorted[i];
                float4 p1, p2, p3;
                if (i1 < e) p1 = g_sorted[i1];
                if (i2 < e) p2 = g_sorted[i2];
                if (i3 < e) p3 = g_sorted[i3];
                {
                    float a = fmaf(p0.x, tx, p0.w);
                    a = fmaf(p0.y, ty, a); a = fmaf(p0.z, tz, a);
                    mn0 = fminf(mn0, a);
                }
                if (i1 < e) {
                    float a = fmaf(p1.x, tx, p1.w);
                    a = fmaf(p1.y, ty, a); a = fmaf(p1.z, tz, a);
                    mn1 = fminf(mn1, a);
                }
                if (i2 < e) {
                    float a = fmaf(p2.x, tx, p2.w);
                    a = fmaf(p2.y, ty, a); a = fmaf(p2.z, tz, a);
                    mn2 = fminf(mn2, a);
                }
                if (i3 < e) {
                    float a = fmaf(p3.x, tx, p3.w);
                    a = fmaf(p3.y, ty, a); a = fmaf(p3.z, tz, a);
                    mn3 = fminf(mn3, a);
                }
            }
        };

        // Phase 1: center CELL only (smallest set, best expected min).
        do_row(scz, scz1);
        float cm = fminf(fminf(mn0, mn1), fminf(mn2, mn3));
        cm = ord2f(__reduce_min_sync(0xFFFFFFFFu, f2ord(cm)));
        const float runb = fminf(THRESH, cm + tsq);

        // Phase 2a: center row z-leftovers, pruned by slab dz^2.
        // (If cz is at the grid edge the corresponding range is empty, so a
        //  wrong-signed dz can never cause a missed visit.)
        {
            const float zb = GMIN + cz * CELL;         // lower edge of center z-cell
            const float dzl = tz - zb;                 // distance to cz-1 slab
            const float dzh = (zb + CELL) - tz;        // distance to cz+1 slab
            if (dzl * dzl < runb) do_row(sA[4], scz);
            if (dzh * dzh < runb) do_row(scz1, eA[4]);
        }

        // Phase 2b: the 8 other rows, pruned by dx^2+dy^2.
#pragma unroll
        for (int k = 0; k < 9; k++) {
            if (k == 4) continue;
            if (bA[k] >= runb) continue;       // provably irrelevant
            do_row(sA[k], eA[k]);
        }

        float mn = fminf(fminf(mn0, mn1), fminf(mn2, mn3));
        mn = ord2f(__reduce_min_sync(0xFFFFFFFFu, f2ord(mn)));
        const float d2 = mn + tsq;
        if (d2 < THRESH) contrib = d2;
    }

    __shared__ float ws[QWARPS];
    __shared__ bool amlast;
    if (lane == 0) ws[wid] = contrib;
    __syncthreads();
    if (threadIdx.x == 0) {
        float s = 0.0f;
#pragma unroll
        for (int k = 0; k < QWARPS; k++) s += ws[k];   // fixed order
        g_blocksum[blockIdx.x] = s;
        __threadfence();
        int t = atomicAdd(&g_ticket, 1);
        amlast = (t == (int)gridDim.x - 1);
    }
    __syncthreads();

    if (amlast) {   // deterministic final reduction by the last-arriving block
        __threadfence();
        float s = 0.0f;
        for (int b = threadIdx.x; b < (int)gridDim.x; b += QBLOCK)
            s += g_blocksum[b];                        // fixed strided partition
#pragma unroll
        for (int o = 16; o > 0; o >>= 1)
            s += __shfl_down_sync(0xFFFFFFFFu, s, o);
        if (lane == 0) ws[wid] = s;
        __syncthreads();
        if (threadIdx.x == 0) {
            float tot = 0.0f;
#pragma unroll
            for (int k = 0; k < QWARPS; k++) tot += ws[k];
            out[0] = tot;
            g_ticket = 0;                              // ready for next replay
        }
    }
}

extern "C" void kernel_launch(void* const* d_in, const int* in_sizes, int n_in,
                              void* d_out, int out_size) {
    const float* scan = (const float*)d_in[0];
    const float* tmpl = (const float*)d_in[1];
    const int N = in_sizes[0] / 3;
    const int M = in_sizes[1] / 3;

    count_kernel<<<(N + 255) / 256, 256>>>(scan, N);
    scan_kernel<<<1, 1024>>>();
    scatter_kernel<<<(N + 255) / 256, 256>>>(scan, N);

    const int qblocks = (M + QWARPS - 1) / QWARPS;
    query_kernel<<<qblocks, QBLOCK>>>(tmpl, M, (float*)d_out);
}